// round 12
// baseline (speedup 1.0000x reference)
#include <cuda_runtime.h>
#include <stdint.h>
#include <math_constants.h>

// WinnerTakeAll: per-row top-k (k=1000), rows of 20000 fp32, 4096 rows.
// Fused single kernel, one CTA/row, NT=256, 8 CTAs/SM. R11 structure with the
// stream loop reshaped to unroll-4 batches (MLP_p1 ~4) to cut cross-CTA
// L1tex-queue spread at occ 8 (B300 spr_max model).
//  1. t_hi = mu+1.751*sigma (~800 sure winners), t_lo = mu+1.514*sigma.
//  2. hot stream: out = v>=t_lo ? v : 0; count c_above (v>=t_hi);
//     band indices [t_lo,t_hi) -> per-thread SMEM slots (~500 total).
//  3. compact band; exact 11/11/10 radix select of the (k-c_above)-th band key;
//     zero the band losers.
//  4. any violation -> exact slow path (full radix, rewrites entire row).

#define DCOLS    20000
#define KKEEP    1000u
#define NT       256
#define NWARP    8
#define NBINS    2048
#define SLOTS    12
#define CAND_CAP 1024
#define ZHI      1.751f
#define ZLO      1.514f

struct Smem {
    union {
        uint16_t sidx[NT * SLOTS];   // 6144 B (hot-loop slots)
        uint32_t hist[NBINS];        // 8192 B (tail/slow-path histogram)
    } u;
    uint32_t segsum[256];            // 1 KB
    uint32_t cand[CAND_CAP];         // 4 KB
    uint16_t cidx[CAND_CAP];         // 2 KB
    float    redsum[NWARP], redsq[NWARP];
    uint32_t wsum[NWARP], woff[NWARP];
    float    t_hi, t_lo;
    uint32_t cand_count, overflow, c_above;
    uint32_t bA, kkA, bB, kkB, bC, kkC, cntC;
};

__device__ __forceinline__ uint32_t f2u(float f) {
    uint32_t b = __float_as_uint(f);
    return b ^ ((b & 0x80000000u) ? 0xFFFFFFFFu : 0x80000000u);
}
__device__ __forceinline__ float u2f(uint32_t u) {
    uint32_t b = (u & 0x80000000u) ? (u ^ 0x80000000u) : (u ^ 0xFFFFFFFFu);
    return __uint_as_float(b);
}

// Warp-aggregated histogram add (ALL 32 lanes participate).
__device__ __forceinline__ void hist_add(uint32_t* hist, uint32_t bin, bool valid) {
    uint32_t key = valid ? bin : 0xFFFFFFFFu;
    unsigned m = __match_any_sync(0xFFFFFFFFu, key);
    int leader = __ffs(m) - 1;
    if (valid && (int)(threadIdx.x & 31) == leader)
        atomicAdd(&hist[bin], (uint32_t)__popc(m));
}

// Serial top-down scan (slow path only; warp 0).
__device__ __forceinline__ void select_from_top(const uint32_t* hist, int nbins, uint32_t kk,
                                                uint32_t* out_bin, uint32_t* out_kk, uint32_t* out_cnt) {
    int lane = threadIdx.x & 31;
    uint32_t cum = 0;
    for (int base = nbins - 32; base >= 0; base -= 32) {
        uint32_t v = hist[base + 31 - lane];
        uint32_t incl = v;
        #pragma unroll
        for (int off = 1; off < 32; off <<= 1) {
            uint32_t t = __shfl_up_sync(0xFFFFFFFFu, incl, off);
            if (lane >= off) incl += t;
        }
        uint32_t total = __shfl_sync(0xFFFFFFFFu, incl, 31);
        unsigned hm = __ballot_sync(0xFFFFFFFFu, cum + incl >= kk);
        if (hm) {
            int l = __ffs(hm) - 1;
            if (lane == l) {
                *out_bin = (uint32_t)(base + 31 - l);
                *out_kk  = kk - cum - (incl - v);
                *out_cnt = v;
            }
            return;
        }
        cum += total;
    }
    if (lane == 0) { *out_bin = 0; *out_kk = 1; *out_cnt = 1; }
}

// Block-parallel select: segment sums (8 bins/seg), then warp 0 scans segments.
__device__ __forceinline__ void select2(Smem* s, const uint32_t* hist, int nbins, uint32_t kk,
                                        uint32_t* out_bin, uint32_t* out_kk, uint32_t* out_cnt,
                                        int tid) {
    int nseg = nbins >> 3;
    const uint4* h4 = reinterpret_cast<const uint4*>(hist);
    for (int i = tid; i < nseg; i += NT) {
        uint4 x = h4[2 * i], y = h4[2 * i + 1];
        s->segsum[i] = x.x + x.y + x.z + x.w + y.x + y.y + y.z + y.w;
    }
    __syncthreads();
    if (tid < 32) {
        int lane = tid;
        uint32_t cum = 0;
        bool done = false;
        for (int base = nseg - 32; base >= 0 && !done; base -= 32) {
            uint32_t v = s->segsum[base + 31 - lane];
            uint32_t incl = v;
            #pragma unroll
            for (int off = 1; off < 32; off <<= 1) {
                uint32_t t = __shfl_up_sync(0xFFFFFFFFu, incl, off);
                if (lane >= off) incl += t;
            }
            uint32_t total = __shfl_sync(0xFFFFFFFFu, incl, 31);
            unsigned hm = __ballot_sync(0xFFFFFFFFu, cum + incl >= kk);
            if (hm) {
                int l = __ffs(hm) - 1;
                if (lane == l) {
                    int seg = base + 31 - l;
                    uint32_t kk_s = kk - cum - (incl - v);
                    for (int b = seg * 8 + 7; b >= seg * 8; b--) {
                        uint32_t c = hist[b];
                        if (kk_s <= c) { *out_bin = (uint32_t)b; *out_kk = kk_s; *out_cnt = c; break; }
                        kk_s -= c;
                    }
                }
                done = true;
            }
            cum += total;
        }
        if (!done && lane == 0) { *out_bin = 0; *out_kk = 1; *out_cnt = 1; }
    }
    __syncthreads();
}

extern "C" __global__ void __launch_bounds__(NT, 8)
wta_kernel(const float* __restrict__ in, float* __restrict__ out, int rows) {
    __shared__ Smem s;

    const int row = blockIdx.x;
    if (row >= rows) return;
    const int tid = threadIdx.x;
    const int lane = tid & 31;
    const int w = tid >> 5;

    const float*  rowf = in + (size_t)row * DCOLS;
    const float4* rowp = reinterpret_cast<const float4*>(rowf);
    float4* outp = reinterpret_cast<float4*>(out + (size_t)row * DCOLS);
    float*  outf = out + (size_t)row * DCOLS;
    const int nvec = DCOLS / 4;                 // 5000
    const int niter = (nvec + NT - 1) / NT;     // 20

    if (tid == 0) { s.cand_count = 0; s.overflow = 0; s.c_above = 0; }

    // ---- phase 1: thresholds from sample mean/std (2048 samples) ----
    {
        float4 a = rowp[tid];
        float4 b = rowp[tid + NT];
        float sum = a.x + a.y + a.z + a.w + b.x + b.y + b.z + b.w;
        float sq = fmaf(a.x, a.x, fmaf(a.y, a.y, fmaf(a.z, a.z, a.w * a.w)));
        sq = fmaf(b.x, b.x, fmaf(b.y, b.y, fmaf(b.z, b.z, fmaf(b.w, b.w, sq))));
        #pragma unroll
        for (int off = 16; off > 0; off >>= 1) {
            sum += __shfl_down_sync(0xFFFFFFFFu, sum, off);
            sq  += __shfl_down_sync(0xFFFFFFFFu, sq,  off);
        }
        if (lane == 0) { s.redsum[w] = sum; s.redsq[w] = sq; }
        __syncthreads();
        if (tid == 0) {
            float ts = 0.f, tq = 0.f;
            #pragma unroll
            for (int i = 0; i < NWARP; i++) { ts += s.redsum[i]; tq += s.redsq[i]; }
            float mu = ts * (1.0f / 2048.0f);
            float var = tq * (1.0f / 2048.0f) - mu * mu;
            float sd = sqrtf(fmaxf(var, 0.0f));
            s.t_hi = fmaf(ZHI, sd, mu);
            s.t_lo = fmaf(ZLO, sd, mu);
        }
        __syncthreads();
    }
    const float t_hi = s.t_hi;
    const float t_lo = s.t_lo;

    // ---- phase 2: hot stream, unroll-4 batches (MLP_p1 ~4, less L1tex spread) ----
    uint32_t nloc = 0;
    uint32_t my_above = 0;
    const uint32_t slotbase = (uint32_t)tid * SLOTS;
    const float NEG = __int_as_float(0xFF800000);
    #pragma unroll 1
    for (int ob = 0; ob < 5; ob++) {
        #pragma unroll
        for (int ib = 0; ib < 4; ib++) {
            int it = ob * 4 + ib;
            int i = tid + it * NT;
            bool valid = i < nvec;
            float4 v = make_float4(NEG, NEG, NEG, NEG);
            if (valid) v = rowp[i];
            float vv[4] = { v.x, v.y, v.z, v.w };
            float ov[4];
            #pragma unroll
            for (int j = 0; j < 4; j++) {
                bool ab = vv[j] >= t_hi;           // sure winner
                bool ge = vv[j] >= t_lo;           // winner or band
                ov[j] = ge ? vv[j] : 0.0f;
                my_above += ab;
                if (ge && !ab) {                   // band candidate
                    if (nloc < SLOTS) s.u.sidx[slotbase + nloc] = (uint16_t)(i * 4 + j);
                    nloc++;
                }
            }
            if (valid) {
                float4 o; o.x = ov[0]; o.y = ov[1]; o.z = ov[2]; o.w = ov[3];
                outp[i] = o;
            }
        }
    }
    uint32_t nstore = nloc < SLOTS ? nloc : SLOTS;
    if (nloc > SLOTS) s.overflow = 1;

    // reduce c_above
    #pragma unroll
    for (int off = 16; off > 0; off >>= 1)
        my_above += __shfl_down_sync(0xFFFFFFFFu, my_above, off);
    if (lane == 0 && my_above) atomicAdd(&s.c_above, my_above);

    // ---- phase 3: block scan of per-thread band counts ----
    uint32_t incl = nstore;
    #pragma unroll
    for (int off = 1; off < 32; off <<= 1) {
        uint32_t x = __shfl_up_sync(0xFFFFFFFFu, incl, off);
        if (lane >= off) incl += x;
    }
    if (lane == 31) s.wsum[w] = incl;
    __syncthreads();
    if (tid < NWARP) {
        uint32_t c = s.wsum[tid];
        uint32_t inc2 = c;
        #pragma unroll
        for (int off = 1; off < NWARP; off <<= 1) {
            uint32_t x = __shfl_up_sync(0x000000FFu, inc2, off);
            if (tid >= off) inc2 += x;
        }
        s.woff[tid] = inc2 - c;
        if (tid == NWARP - 1) s.cand_count = inc2;
    }
    __syncthreads();

    // ---- phase 4: gather band candidates into compact arrays ----
    {
        uint32_t myoff = s.woff[w] + (incl - nstore);
        for (uint32_t n = 0; n < nstore; n++) {
            uint32_t pos = myoff + n;
            if (pos < CAND_CAP) {
                uint16_t idx = s.u.sidx[slotbase + n];
                s.cand[pos] = f2u(rowf[idx]);
                s.cidx[pos] = idx;
            }
        }
    }
    __syncthreads();

    const uint32_t ccount = s.cand_count;
    const uint32_t c_above = s.c_above;
    bool fast = (!s.overflow) && (c_above < KKEEP) &&
                (c_above + ccount >= KKEEP) && (ccount <= CAND_CAP);

    if (!fast) {
        // ================= SLOW PATH (rare; rewrites entire row) =================
        {
            uint4* h4 = reinterpret_cast<uint4*>(s.u.hist);
            h4[tid * 2] = make_uint4(0, 0, 0, 0);
            h4[tid * 2 + 1] = make_uint4(0, 0, 0, 0);
        }
        if (tid == 0) s.cand_count = 0;
        __syncthreads();

        #pragma unroll 1
        for (int it = 0; it < niter; it++) {
            int i = tid + it * NT;
            bool valid = i < nvec;
            uint32_t u0 = 0, u1 = 0, u2 = 0, u3 = 0;
            if (valid) {
                float4 v = rowp[i];
                u0 = f2u(v.x); u1 = f2u(v.y); u2 = f2u(v.z); u3 = f2u(v.w);
            }
            hist_add(s.u.hist, u0 >> 21, valid);
            hist_add(s.u.hist, u1 >> 21, valid);
            hist_add(s.u.hist, u2 >> 21, valid);
            hist_add(s.u.hist, u3 >> 21, valid);
        }
        __syncthreads();
        if (tid < 32) select_from_top(s.u.hist, NBINS, KKEEP, &s.bA, &s.kkA, &s.cntC);
        __syncthreads();
        const uint32_t b1 = s.bA;
        const uint32_t kk1 = s.kkA;

        #pragma unroll 1
        for (int it = 0; it < niter; it++) {
            int i = tid + it * NT;
            if (i >= nvec) break;
            float4 v = rowp[i];
            float vv[4] = { v.x, v.y, v.z, v.w };
            uint32_t uu[4] = { f2u(v.x), f2u(v.y), f2u(v.z), f2u(v.w) };
            float ov[4];
            #pragma unroll
            for (int j = 0; j < 4; j++) {
                uint32_t bin = uu[j] >> 21;
                ov[j] = (bin > b1) ? vv[j] : 0.0f;
                if (bin == b1) {
                    uint32_t pos = atomicAdd(&s.cand_count, 1u);
                    if (pos < CAND_CAP) { s.cand[pos] = uu[j]; s.cidx[pos] = (uint16_t)(i * 4 + j); }
                }
            }
            float4 o; o.x = ov[0]; o.y = ov[1]; o.z = ov[2]; o.w = ov[3];
            outp[i] = o;
        }
        __syncthreads();

        const uint32_t cc2 = s.cand_count;
        const bool use_cand = (cc2 <= CAND_CAP);
        const int nitems = use_cand ? (int)cc2 : DCOLS;
        const int niterB = (nitems + NT - 1) / NT;

        {
            uint4* h4 = reinterpret_cast<uint4*>(s.u.hist);
            h4[tid * 2] = make_uint4(0, 0, 0, 0);
            h4[tid * 2 + 1] = make_uint4(0, 0, 0, 0);
        }
        __syncthreads();
        #pragma unroll 1
        for (int it = 0; it < niterB; it++) {
            int i = tid + it * NT;
            bool valid = i < nitems;
            uint32_t u = 0;
            if (valid) u = use_cand ? s.cand[i] : f2u(rowf[i]);
            valid = valid && (use_cand || ((u >> 21) == b1));
            hist_add(s.u.hist, (u >> 10) & 0x7FFu, valid);
        }
        __syncthreads();
        if (tid < 32) select_from_top(s.u.hist, NBINS, kk1, &s.bB, &s.kkB, &s.cntC);
        __syncthreads();
        const uint32_t b2 = s.bB;
        const uint32_t kk2 = s.kkB;
        const uint32_t pref22 = (b1 << 11) | b2;

        for (int i = tid; i < 1024; i += NT) s.u.hist[i] = 0;
        __syncthreads();
        #pragma unroll 1
        for (int it = 0; it < niterB; it++) {
            int i = tid + it * NT;
            bool valid = i < nitems;
            uint32_t u = 0;
            if (valid) u = use_cand ? s.cand[i] : f2u(rowf[i]);
            valid = valid && ((u >> 10) == pref22);
            hist_add(s.u.hist, u & 0x3FFu, valid);
        }
        __syncthreads();
        if (tid < 32) select_from_top(s.u.hist, 1024, kk2, &s.bC, &s.kkC, &s.cntC);
        __syncthreads();

        const uint32_t u_t = (b1 << 21) | (b2 << 10) | s.bC;
        const uint32_t A = s.kkC;
        const uint32_t T = s.cntC;
        const bool keep_all_ties = (A == T);

        if (use_cand) {
            for (uint32_t q = tid; q < cc2; q += NT) {
                uint32_t u = s.cand[q];
                bool keep = (u > u_t);
                if (!keep && u == u_t) {
                    if (keep_all_ties) keep = true;
                    else {
                        uint32_t rank = 0;
                        for (uint32_t p = 0; p < cc2; p++)
                            rank += (s.cand[p] == u_t && s.cidx[p] < s.cidx[q]);
                        keep = (rank < A);
                    }
                }
                if (keep) outf[s.cidx[q]] = u2f(u);
            }
        } else {
            for (int i = tid; i < DCOLS; i += NT) {
                uint32_t u = f2u(rowf[i]);
                if ((u >> 21) != b1) continue;
                bool keep = (u > u_t);
                if (!keep && u == u_t) {
                    if (keep_all_ties) keep = true;
                    else {
                        uint32_t rank = 0;
                        for (int q = 0; q < i; q++) rank += (f2u(rowf[q]) == u_t);
                        keep = (rank < A);
                    }
                }
                if (keep) outf[i] = u2f(u);
            }
        }
        return;
    }

    // ===== FAST PATH: exact (k - c_above)-th among band candidates =====
    {
        uint4* h4 = reinterpret_cast<uint4*>(s.u.hist);
        h4[tid * 2] = make_uint4(0, 0, 0, 0);
        h4[tid * 2 + 1] = make_uint4(0, 0, 0, 0);
    }
    __syncthreads();

    const uint32_t kk = KKEEP - c_above;
    const int niterC = ((int)ccount + NT - 1) / NT;

    #pragma unroll 1
    for (int it = 0; it < niterC; it++) {
        int i = tid + it * NT;
        bool valid = i < (int)ccount;
        uint32_t u = valid ? s.cand[i] : 0;
        hist_add(s.u.hist, u >> 21, valid);
    }
    __syncthreads();
    select2(&s, s.u.hist, NBINS, kk, &s.bA, &s.kkA, &s.cntC, tid);
    const uint32_t b1 = s.bA;
    const uint32_t kk1 = s.kkA;

    {
        uint4* h4 = reinterpret_cast<uint4*>(s.u.hist);
        h4[tid * 2] = make_uint4(0, 0, 0, 0);
        h4[tid * 2 + 1] = make_uint4(0, 0, 0, 0);
    }
    __syncthreads();
    #pragma unroll 1
    for (int it = 0; it < niterC; it++) {
        int i = tid + it * NT;
        bool valid = i < (int)ccount;
        uint32_t u = valid ? s.cand[i] : 0;
        valid = valid && ((u >> 21) == b1);
        hist_add(s.u.hist, (u >> 10) & 0x7FFu, valid);
    }
    __syncthreads();
    select2(&s, s.u.hist, NBINS, kk1, &s.bB, &s.kkB, &s.cntC, tid);
    const uint32_t b2 = s.bB;
    const uint32_t kk2 = s.kkB;
    const uint32_t pref22 = (b1 << 11) | b2;

    for (int i = tid; i < 1024; i += NT) s.u.hist[i] = 0;
    __syncthreads();
    #pragma unroll 1
    for (int it = 0; it < niterC; it++) {
        int i = tid + it * NT;
        bool valid = i < (int)ccount;
        uint32_t u = valid ? s.cand[i] : 0;
        valid = valid && ((u >> 10) == pref22);
        hist_add(s.u.hist, u & 0x3FFu, valid);
    }
    __syncthreads();
    select2(&s, s.u.hist, 1024, kk2, &s.bC, &s.kkC, &s.cntC, tid);

    const uint32_t u_t = (b1 << 21) | (b2 << 10) | s.bC;   // exact k-th largest key
    const uint32_t A = s.kkC;
    const uint32_t T = s.cntC;
    const bool keep_all_ties = (A == T);

    // zero band losers (output already holds v for winners + band)
    for (uint32_t q = tid; q < ccount; q += NT) {
        uint32_t u = s.cand[q];
        bool lose = (u < u_t);
        if (!lose && u == u_t && !keep_all_ties) {
            uint32_t rank = 0;
            for (uint32_t p = 0; p < ccount; p++)
                rank += (s.cand[p] == u_t && s.cidx[p] < s.cidx[q]);
            lose = (rank >= A);
        }
        if (lose) outf[s.cidx[q]] = 0.0f;
    }
}

extern "C" void kernel_launch(void* const* d_in, const int* in_sizes, int n_in,
                              void* d_out, int out_size) {
    const float* in = (const float*)d_in[0];
    float* out = (float*)d_out;
    int rows = in_sizes[0] / DCOLS;   // 4096
    wta_kernel<<<rows, NT>>>(in, out, rows);
}

// round 13
// speedup vs baseline: 1.1315x; 1.1315x over previous
#include <cuda_runtime.h>
#include <stdint.h>
#include <math_constants.h>

// WinnerTakeAll: per-row top-k (k=1000), rows of 20000 fp32, 4096 rows.
// R11 band kernel at NT=512, 4 CTAs/SM (same 2048 thr/SM) to cut wave
// quantization: 4096 rows / 592 slots = 6.92 -> makespan 7 (1.2% loss) vs
// 3.46 -> 4 (13.5% loss) at NT=256/occ8.
//  1. t_hi = mu+1.751*sigma, t_lo = mu+1.514*sigma from 2048 samples.
//  2. hot stream (full unroll x10): out = v>=t_lo ? v : 0; count c_above;
//     band indices [t_lo,t_hi) -> per-thread SMEM slots (~500 total).
//  3. compact band; exact 11/11/10 radix select of (k-c_above)-th band key;
//     zero band losers.
//  4. any violation -> exact slow path (full radix, rewrites entire row).

#define DCOLS    20000
#define KKEEP    1000u
#define NT       512
#define NWARP    16
#define NBINS    2048
#define SLOTS    12
#define CAND_CAP 1024
#define ZHI      1.751f
#define ZLO      1.514f

struct Smem {
    union {
        uint16_t sidx[NT * SLOTS];   // 12288 B (hot-loop slots)
        uint32_t hist[NBINS];        // 8192 B  (tail/slow-path histogram)
    } u;
    uint32_t segsum[256];            // 1 KB
    uint32_t cand[CAND_CAP];         // 4 KB
    uint16_t cidx[CAND_CAP];         // 2 KB
    float    redsum[NWARP], redsq[NWARP];
    uint32_t wsum[NWARP], woff[NWARP];
    float    t_hi, t_lo;
    uint32_t cand_count, overflow, c_above;
    uint32_t bA, kkA, bB, kkB, bC, kkC, cntC;
};

__device__ __forceinline__ uint32_t f2u(float f) {
    uint32_t b = __float_as_uint(f);
    return b ^ ((b & 0x80000000u) ? 0xFFFFFFFFu : 0x80000000u);
}
__device__ __forceinline__ float u2f(uint32_t u) {
    uint32_t b = (u & 0x80000000u) ? (u ^ 0x80000000u) : (u ^ 0xFFFFFFFFu);
    return __uint_as_float(b);
}

// Warp-aggregated histogram add (ALL 32 lanes participate).
__device__ __forceinline__ void hist_add(uint32_t* hist, uint32_t bin, bool valid) {
    uint32_t key = valid ? bin : 0xFFFFFFFFu;
    unsigned m = __match_any_sync(0xFFFFFFFFu, key);
    int leader = __ffs(m) - 1;
    if (valid && (int)(threadIdx.x & 31) == leader)
        atomicAdd(&hist[bin], (uint32_t)__popc(m));
}

// Serial top-down scan (slow path only; warp 0).
__device__ __forceinline__ void select_from_top(const uint32_t* hist, int nbins, uint32_t kk,
                                                uint32_t* out_bin, uint32_t* out_kk, uint32_t* out_cnt) {
    int lane = threadIdx.x & 31;
    uint32_t cum = 0;
    for (int base = nbins - 32; base >= 0; base -= 32) {
        uint32_t v = hist[base + 31 - lane];
        uint32_t incl = v;
        #pragma unroll
        for (int off = 1; off < 32; off <<= 1) {
            uint32_t t = __shfl_up_sync(0xFFFFFFFFu, incl, off);
            if (lane >= off) incl += t;
        }
        uint32_t total = __shfl_sync(0xFFFFFFFFu, incl, 31);
        unsigned hm = __ballot_sync(0xFFFFFFFFu, cum + incl >= kk);
        if (hm) {
            int l = __ffs(hm) - 1;
            if (lane == l) {
                *out_bin = (uint32_t)(base + 31 - l);
                *out_kk  = kk - cum - (incl - v);
                *out_cnt = v;
            }
            return;
        }
        cum += total;
    }
    if (lane == 0) { *out_bin = 0; *out_kk = 1; *out_cnt = 1; }
}

// Block-parallel select: segment sums (8 bins/seg), then warp 0 scans segments.
__device__ __forceinline__ void select2(Smem* s, const uint32_t* hist, int nbins, uint32_t kk,
                                        uint32_t* out_bin, uint32_t* out_kk, uint32_t* out_cnt,
                                        int tid) {
    int nseg = nbins >> 3;
    const uint4* h4 = reinterpret_cast<const uint4*>(hist);
    for (int i = tid; i < nseg; i += NT) {
        uint4 x = h4[2 * i], y = h4[2 * i + 1];
        s->segsum[i] = x.x + x.y + x.z + x.w + y.x + y.y + y.z + y.w;
    }
    __syncthreads();
    if (tid < 32) {
        int lane = tid;
        uint32_t cum = 0;
        bool done = false;
        for (int base = nseg - 32; base >= 0 && !done; base -= 32) {
            uint32_t v = s->segsum[base + 31 - lane];
            uint32_t incl = v;
            #pragma unroll
            for (int off = 1; off < 32; off <<= 1) {
                uint32_t t = __shfl_up_sync(0xFFFFFFFFu, incl, off);
                if (lane >= off) incl += t;
            }
            uint32_t total = __shfl_sync(0xFFFFFFFFu, incl, 31);
            unsigned hm = __ballot_sync(0xFFFFFFFFu, cum + incl >= kk);
            if (hm) {
                int l = __ffs(hm) - 1;
                if (lane == l) {
                    int seg = base + 31 - l;
                    uint32_t kk_s = kk - cum - (incl - v);
                    for (int b = seg * 8 + 7; b >= seg * 8; b--) {
                        uint32_t c = hist[b];
                        if (kk_s <= c) { *out_bin = (uint32_t)b; *out_kk = kk_s; *out_cnt = c; break; }
                        kk_s -= c;
                    }
                }
                done = true;
            }
            cum += total;
        }
        if (!done && lane == 0) { *out_bin = 0; *out_kk = 1; *out_cnt = 1; }
    }
    __syncthreads();
}

extern "C" __global__ void __launch_bounds__(NT, 4)
wta_kernel(const float* __restrict__ in, float* __restrict__ out, int rows) {
    __shared__ Smem s;

    const int row = blockIdx.x;
    if (row >= rows) return;
    const int tid = threadIdx.x;
    const int lane = tid & 31;
    const int w = tid >> 5;

    const float*  rowf = in + (size_t)row * DCOLS;
    const float4* rowp = reinterpret_cast<const float4*>(rowf);
    float4* outp = reinterpret_cast<float4*>(out + (size_t)row * DCOLS);
    float*  outf = out + (size_t)row * DCOLS;
    const int nvec = DCOLS / 4;                 // 5000
    const int niter = (nvec + NT - 1) / NT;     // 10

    if (tid == 0) { s.cand_count = 0; s.overflow = 0; s.c_above = 0; }

    // ---- phase 1: thresholds from sample mean/std (2048 samples, 1 ld/thread) ----
    {
        float4 a = rowp[tid];
        float sum = a.x + a.y + a.z + a.w;
        float sq = fmaf(a.x, a.x, fmaf(a.y, a.y, fmaf(a.z, a.z, a.w * a.w)));
        #pragma unroll
        for (int off = 16; off > 0; off >>= 1) {
            sum += __shfl_down_sync(0xFFFFFFFFu, sum, off);
            sq  += __shfl_down_sync(0xFFFFFFFFu, sq,  off);
        }
        if (lane == 0) { s.redsum[w] = sum; s.redsq[w] = sq; }
        __syncthreads();
        if (tid == 0) {
            float ts = 0.f, tq = 0.f;
            #pragma unroll
            for (int i = 0; i < NWARP; i++) { ts += s.redsum[i]; tq += s.redsq[i]; }
            float mu = ts * (1.0f / 2048.0f);
            float var = tq * (1.0f / 2048.0f) - mu * mu;
            float sd = sqrtf(fmaxf(var, 0.0f));
            s.t_hi = fmaf(ZHI, sd, mu);
            s.t_lo = fmaf(ZLO, sd, mu);
        }
        __syncthreads();
    }
    const float t_hi = s.t_hi;
    const float t_lo = s.t_lo;

    // ---- phase 2: hot stream (full unroll x10, R11 form) ----
    uint32_t nloc = 0;
    uint32_t my_above = 0;
    const uint32_t slotbase = (uint32_t)tid * SLOTS;
    const float NEG = __int_as_float(0xFF800000);
    #pragma unroll
    for (int it = 0; it < 10; it++) {
        int i = tid + it * NT;
        bool valid = i < nvec;
        float4 v = make_float4(NEG, NEG, NEG, NEG);
        if (valid) v = rowp[i];
        float vv[4] = { v.x, v.y, v.z, v.w };
        float ov[4];
        #pragma unroll
        for (int j = 0; j < 4; j++) {
            bool ab = vv[j] >= t_hi;           // sure winner
            bool ge = vv[j] >= t_lo;           // winner or band
            ov[j] = ge ? vv[j] : 0.0f;
            my_above += ab;
            if (ge && !ab) {                   // band candidate
                if (nloc < SLOTS) s.u.sidx[slotbase + nloc] = (uint16_t)(i * 4 + j);
                nloc++;
            }
        }
        if (valid) {
            float4 o; o.x = ov[0]; o.y = ov[1]; o.z = ov[2]; o.w = ov[3];
            outp[i] = o;
        }
    }
    uint32_t nstore = nloc < SLOTS ? nloc : SLOTS;
    if (nloc > SLOTS) s.overflow = 1;

    // reduce c_above
    #pragma unroll
    for (int off = 16; off > 0; off >>= 1)
        my_above += __shfl_down_sync(0xFFFFFFFFu, my_above, off);
    if (lane == 0 && my_above) atomicAdd(&s.c_above, my_above);

    // ---- phase 3: block scan of per-thread band counts ----
    uint32_t incl = nstore;
    #pragma unroll
    for (int off = 1; off < 32; off <<= 1) {
        uint32_t x = __shfl_up_sync(0xFFFFFFFFu, incl, off);
        if (lane >= off) incl += x;
    }
    if (lane == 31) s.wsum[w] = incl;
    __syncthreads();
    if (tid < NWARP) {
        uint32_t c = s.wsum[tid];
        uint32_t inc2 = c;
        #pragma unroll
        for (int off = 1; off < NWARP; off <<= 1) {
            uint32_t x = __shfl_up_sync(0x0000FFFFu, inc2, off);
            if (tid >= off) inc2 += x;
        }
        s.woff[tid] = inc2 - c;
        if (tid == NWARP - 1) s.cand_count = inc2;
    }
    __syncthreads();

    // ---- phase 4: gather band candidates into compact arrays ----
    {
        uint32_t myoff = s.woff[w] + (incl - nstore);
        for (uint32_t n = 0; n < nstore; n++) {
            uint32_t pos = myoff + n;
            if (pos < CAND_CAP) {
                uint16_t idx = s.u.sidx[slotbase + n];
                s.cand[pos] = f2u(rowf[idx]);
                s.cidx[pos] = idx;
            }
        }
    }
    __syncthreads();

    const uint32_t ccount = s.cand_count;
    const uint32_t c_above = s.c_above;
    bool fast = (!s.overflow) && (c_above < KKEEP) &&
                (c_above + ccount >= KKEEP) && (ccount <= CAND_CAP);

    if (!fast) {
        // ================= SLOW PATH (rare; rewrites entire row) =================
        reinterpret_cast<uint4*>(s.u.hist)[tid & 511] = make_uint4(0, 0, 0, 0);
        if (tid == 0) s.cand_count = 0;
        __syncthreads();

        #pragma unroll 1
        for (int it = 0; it < niter; it++) {
            int i = tid + it * NT;
            bool valid = i < nvec;
            uint32_t u0 = 0, u1 = 0, u2 = 0, u3 = 0;
            if (valid) {
                float4 v = rowp[i];
                u0 = f2u(v.x); u1 = f2u(v.y); u2 = f2u(v.z); u3 = f2u(v.w);
            }
            hist_add(s.u.hist, u0 >> 21, valid);
            hist_add(s.u.hist, u1 >> 21, valid);
            hist_add(s.u.hist, u2 >> 21, valid);
            hist_add(s.u.hist, u3 >> 21, valid);
        }
        __syncthreads();
        if (tid < 32) select_from_top(s.u.hist, NBINS, KKEEP, &s.bA, &s.kkA, &s.cntC);
        __syncthreads();
        const uint32_t b1 = s.bA;
        const uint32_t kk1 = s.kkA;

        #pragma unroll 1
        for (int it = 0; it < niter; it++) {
            int i = tid + it * NT;
            if (i >= nvec) break;
            float4 v = rowp[i];
            float vv[4] = { v.x, v.y, v.z, v.w };
            uint32_t uu[4] = { f2u(v.x), f2u(v.y), f2u(v.z), f2u(v.w) };
            float ov[4];
            #pragma unroll
            for (int j = 0; j < 4; j++) {
                uint32_t bin = uu[j] >> 21;
                ov[j] = (bin > b1) ? vv[j] : 0.0f;
                if (bin == b1) {
                    uint32_t pos = atomicAdd(&s.cand_count, 1u);
                    if (pos < CAND_CAP) { s.cand[pos] = uu[j]; s.cidx[pos] = (uint16_t)(i * 4 + j); }
                }
            }
            float4 o; o.x = ov[0]; o.y = ov[1]; o.z = ov[2]; o.w = ov[3];
            outp[i] = o;
        }
        __syncthreads();

        const uint32_t cc2 = s.cand_count;
        const bool use_cand = (cc2 <= CAND_CAP);
        const int nitems = use_cand ? (int)cc2 : DCOLS;
        const int niterB = (nitems + NT - 1) / NT;

        reinterpret_cast<uint4*>(s.u.hist)[tid & 511] = make_uint4(0, 0, 0, 0);
        __syncthreads();
        #pragma unroll 1
        for (int it = 0; it < niterB; it++) {
            int i = tid + it * NT;
            bool valid = i < nitems;
            uint32_t u = 0;
            if (valid) u = use_cand ? s.cand[i] : f2u(rowf[i]);
            valid = valid && (use_cand || ((u >> 21) == b1));
            hist_add(s.u.hist, (u >> 10) & 0x7FFu, valid);
        }
        __syncthreads();
        if (tid < 32) select_from_top(s.u.hist, NBINS, kk1, &s.bB, &s.kkB, &s.cntC);
        __syncthreads();
        const uint32_t b2 = s.bB;
        const uint32_t kk2 = s.kkB;
        const uint32_t pref22 = (b1 << 11) | b2;

        for (int i = tid; i < 1024; i += NT) s.u.hist[i] = 0;
        __syncthreads();
        #pragma unroll 1
        for (int it = 0; it < niterB; it++) {
            int i = tid + it * NT;
            bool valid = i < nitems;
            uint32_t u = 0;
            if (valid) u = use_cand ? s.cand[i] : f2u(rowf[i]);
            valid = valid && ((u >> 10) == pref22);
            hist_add(s.u.hist, u & 0x3FFu, valid);
        }
        __syncthreads();
        if (tid < 32) select_from_top(s.u.hist, 1024, kk2, &s.bC, &s.kkC, &s.cntC);
        __syncthreads();

        const uint32_t u_t = (b1 << 21) | (b2 << 10) | s.bC;
        const uint32_t A = s.kkC;
        const uint32_t T = s.cntC;
        const bool keep_all_ties = (A == T);

        if (use_cand) {
            for (uint32_t q = tid; q < cc2; q += NT) {
                uint32_t u = s.cand[q];
                bool keep = (u > u_t);
                if (!keep && u == u_t) {
                    if (keep_all_ties) keep = true;
                    else {
                        uint32_t rank = 0;
                        for (uint32_t p = 0; p < cc2; p++)
                            rank += (s.cand[p] == u_t && s.cidx[p] < s.cidx[q]);
                        keep = (rank < A);
                    }
                }
                if (keep) outf[s.cidx[q]] = u2f(u);
            }
        } else {
            for (int i = tid; i < DCOLS; i += NT) {
                uint32_t u = f2u(rowf[i]);
                if ((u >> 21) != b1) continue;
                bool keep = (u > u_t);
                if (!keep && u == u_t) {
                    if (keep_all_ties) keep = true;
                    else {
                        uint32_t rank = 0;
                        for (int q = 0; q < i; q++) rank += (f2u(rowf[q]) == u_t);
                        keep = (rank < A);
                    }
                }
                if (keep) outf[i] = u2f(u);
            }
        }
        return;
    }

    // ===== FAST PATH: exact (k - c_above)-th among band candidates =====
    reinterpret_cast<uint4*>(s.u.hist)[tid & 511] = make_uint4(0, 0, 0, 0);
    __syncthreads();

    const uint32_t kk = KKEEP - c_above;
    const int niterC = ((int)ccount + NT - 1) / NT;

    #pragma unroll 1
    for (int it = 0; it < niterC; it++) {
        int i = tid + it * NT;
        bool valid = i < (int)ccount;
        uint32_t u = valid ? s.cand[i] : 0;
        hist_add(s.u.hist, u >> 21, valid);
    }
    __syncthreads();
    select2(&s, s.u.hist, NBINS, kk, &s.bA, &s.kkA, &s.cntC, tid);
    const uint32_t b1 = s.bA;
    const uint32_t kk1 = s.kkA;

    reinterpret_cast<uint4*>(s.u.hist)[tid & 511] = make_uint4(0, 0, 0, 0);
    __syncthreads();
    #pragma unroll 1
    for (int it = 0; it < niterC; it++) {
        int i = tid + it * NT;
        bool valid = i < (int)ccount;
        uint32_t u = valid ? s.cand[i] : 0;
        valid = valid && ((u >> 21) == b1);
        hist_add(s.u.hist, (u >> 10) & 0x7FFu, valid);
    }
    __syncthreads();
    select2(&s, s.u.hist, NBINS, kk1, &s.bB, &s.kkB, &s.cntC, tid);
    const uint32_t b2 = s.bB;
    const uint32_t kk2 = s.kkB;
    const uint32_t pref22 = (b1 << 11) | b2;

    for (int i = tid; i < 1024; i += NT) s.u.hist[i] = 0;
    __syncthreads();
    #pragma unroll 1
    for (int it = 0; it < niterC; it++) {
        int i = tid + it * NT;
        bool valid = i < (int)ccount;
        uint32_t u = valid ? s.cand[i] : 0;
        valid = valid && ((u >> 10) == pref22);
        hist_add(s.u.hist, u & 0x3FFu, valid);
    }
    __syncthreads();
    select2(&s, s.u.hist, 1024, kk2, &s.bC, &s.kkC, &s.cntC, tid);

    const uint32_t u_t = (b1 << 21) | (b2 << 10) | s.bC;   // exact k-th largest key
    const uint32_t A = s.kkC;
    const uint32_t T = s.cntC;
    const bool keep_all_ties = (A == T);

    // zero band losers (output already holds v for winners + band)
    for (uint32_t q = tid; q < ccount; q += NT) {
        uint32_t u = s.cand[q];
        bool lose = (u < u_t);
        if (!lose && u == u_t && !keep_all_ties) {
            uint32_t rank = 0;
            for (uint32_t p = 0; p < ccount; p++)
                rank += (s.cand[p] == u_t && s.cidx[p] < s.cidx[q]);
            lose = (rank >= A);
        }
        if (lose) outf[s.cidx[q]] = 0.0f;
    }
}

extern "C" void kernel_launch(void* const* d_in, const int* in_sizes, int n_in,
                              void* d_out, int out_size) {
    const float* in = (const float*)d_in[0];
    float* out = (float*)d_out;
    int rows = in_sizes[0] / DCOLS;   // 4096
    wta_kernel<<<rows, NT>>>(in, out, rows);
}

// round 14
// speedup vs baseline: 1.1719x; 1.0357x over previous
#include <cuda_runtime.h>
#include <stdint.h>
#include <math_constants.h>

// WinnerTakeAll: per-row top-k (k=1000), rows of 20000 fp32, 4096 rows.
// NT=512, 4 CTAs/SM (R13 config). Band select tail upgraded: candidates are
// normalized to [0, R) (R = key-range of the band) before binning, so ONE
// 11-bit hist pass + ONE select2 resolves to a bin with <=32 candidates,
// finished by a warp-register exact selection. Fallback to 3-pass raw-key
// radix if the bin is pathologically full; full slow path on any violation.

#define DCOLS    20000
#define KKEEP    1000u
#define NT       512
#define NWARP    16
#define NBINS    2048
#define SLOTS    12
#define CAND_CAP 1024
#define ZHI      1.751f
#define ZLO      1.514f

struct Smem {
    union {
        uint16_t sidx[NT * SLOTS];   // 12288 B (hot-loop slots)
        uint32_t hist[NBINS];        // 8192 B  (tail/slow-path histogram)
    } u;
    uint32_t segsum[256];            // 1 KB (select2 scratch + tie-collect buffer)
    uint32_t cand[CAND_CAP];         // 4 KB
    uint16_t cidx[CAND_CAP];         // 2 KB
    float    redsum[NWARP], redsq[NWARP];
    uint32_t wsum[NWARP], woff[NWARP];
    float    t_hi, t_lo;
    uint32_t cand_count, overflow, c_above, tcnt;
    uint32_t bA, kkA, bB, kkB, bC, kkC, cntC;
};

__device__ __forceinline__ uint32_t f2u(float f) {
    uint32_t b = __float_as_uint(f);
    return b ^ ((b & 0x80000000u) ? 0xFFFFFFFFu : 0x80000000u);
}
__device__ __forceinline__ float u2f(uint32_t u) {
    uint32_t b = (u & 0x80000000u) ? (u ^ 0x80000000u) : (u ^ 0xFFFFFFFFu);
    return __uint_as_float(b);
}

// Warp-aggregated histogram add (ALL 32 lanes participate).
__device__ __forceinline__ void hist_add(uint32_t* hist, uint32_t bin, bool valid) {
    uint32_t key = valid ? bin : 0xFFFFFFFFu;
    unsigned m = __match_any_sync(0xFFFFFFFFu, key);
    int leader = __ffs(m) - 1;
    if (valid && (int)(threadIdx.x & 31) == leader)
        atomicAdd(&hist[bin], (uint32_t)__popc(m));
}

// Serial top-down scan (slow path only; warp 0).
__device__ __forceinline__ void select_from_top(const uint32_t* hist, int nbins, uint32_t kk,
                                                uint32_t* out_bin, uint32_t* out_kk, uint32_t* out_cnt) {
    int lane = threadIdx.x & 31;
    uint32_t cum = 0;
    for (int base = nbins - 32; base >= 0; base -= 32) {
        uint32_t v = hist[base + 31 - lane];
        uint32_t incl = v;
        #pragma unroll
        for (int off = 1; off < 32; off <<= 1) {
            uint32_t t = __shfl_up_sync(0xFFFFFFFFu, incl, off);
            if (lane >= off) incl += t;
        }
        uint32_t total = __shfl_sync(0xFFFFFFFFu, incl, 31);
        unsigned hm = __ballot_sync(0xFFFFFFFFu, cum + incl >= kk);
        if (hm) {
            int l = __ffs(hm) - 1;
            if (lane == l) {
                *out_bin = (uint32_t)(base + 31 - l);
                *out_kk  = kk - cum - (incl - v);
                *out_cnt = v;
            }
            return;
        }
        cum += total;
    }
    if (lane == 0) { *out_bin = 0; *out_kk = 1; *out_cnt = 1; }
}

// Block-parallel select: segment sums (8 bins/seg), then warp 0 scans segments.
__device__ __forceinline__ void select2(Smem* s, const uint32_t* hist, int nbins, uint32_t kk,
                                        uint32_t* out_bin, uint32_t* out_kk, uint32_t* out_cnt,
                                        int tid) {
    int nseg = nbins >> 3;
    const uint4* h4 = reinterpret_cast<const uint4*>(hist);
    for (int i = tid; i < nseg; i += NT) {
        uint4 x = h4[2 * i], y = h4[2 * i + 1];
        s->segsum[i] = x.x + x.y + x.z + x.w + y.x + y.y + y.z + y.w;
    }
    __syncthreads();
    if (tid < 32) {
        int lane = tid;
        uint32_t cum = 0;
        bool done = false;
        for (int base = nseg - 32; base >= 0 && !done; base -= 32) {
            uint32_t v = s->segsum[base + 31 - lane];
            uint32_t incl = v;
            #pragma unroll
            for (int off = 1; off < 32; off <<= 1) {
                uint32_t t = __shfl_up_sync(0xFFFFFFFFu, incl, off);
                if (lane >= off) incl += t;
            }
            uint32_t total = __shfl_sync(0xFFFFFFFFu, incl, 31);
            unsigned hm = __ballot_sync(0xFFFFFFFFu, cum + incl >= kk);
            if (hm) {
                int l = __ffs(hm) - 1;
                if (lane == l) {
                    int seg = base + 31 - l;
                    uint32_t kk_s = kk - cum - (incl - v);
                    for (int b = seg * 8 + 7; b >= seg * 8; b--) {
                        uint32_t c = hist[b];
                        if (kk_s <= c) { *out_bin = (uint32_t)b; *out_kk = kk_s; *out_cnt = c; break; }
                        kk_s -= c;
                    }
                }
                done = true;
            }
            cum += total;
        }
        if (!done && lane == 0) { *out_bin = 0; *out_kk = 1; *out_cnt = 1; }
    }
    __syncthreads();
}

extern "C" __global__ void __launch_bounds__(NT, 4)
wta_kernel(const float* __restrict__ in, float* __restrict__ out, int rows) {
    __shared__ Smem s;

    const int row = blockIdx.x;
    if (row >= rows) return;
    const int tid = threadIdx.x;
    const int lane = tid & 31;
    const int w = tid >> 5;

    const float*  rowf = in + (size_t)row * DCOLS;
    const float4* rowp = reinterpret_cast<const float4*>(rowf);
    float4* outp = reinterpret_cast<float4*>(out + (size_t)row * DCOLS);
    float*  outf = out + (size_t)row * DCOLS;
    const int nvec = DCOLS / 4;                 // 5000
    const int niter = (nvec + NT - 1) / NT;     // 10

    if (tid == 0) { s.cand_count = 0; s.overflow = 0; s.c_above = 0; s.tcnt = 0; }

    // ---- phase 1: thresholds from sample mean/std (2048 samples, 1 ld/thread) ----
    {
        float4 a = rowp[tid];
        float sum = a.x + a.y + a.z + a.w;
        float sq = fmaf(a.x, a.x, fmaf(a.y, a.y, fmaf(a.z, a.z, a.w * a.w)));
        #pragma unroll
        for (int off = 16; off > 0; off >>= 1) {
            sum += __shfl_down_sync(0xFFFFFFFFu, sum, off);
            sq  += __shfl_down_sync(0xFFFFFFFFu, sq,  off);
        }
        if (lane == 0) { s.redsum[w] = sum; s.redsq[w] = sq; }
        __syncthreads();
        if (tid == 0) {
            float ts = 0.f, tq = 0.f;
            #pragma unroll
            for (int i = 0; i < NWARP; i++) { ts += s.redsum[i]; tq += s.redsq[i]; }
            float mu = ts * (1.0f / 2048.0f);
            float var = tq * (1.0f / 2048.0f) - mu * mu;
            float sd = sqrtf(fmaxf(var, 0.0f));
            s.t_hi = fmaf(ZHI, sd, mu);
            s.t_lo = fmaf(ZLO, sd, mu);
        }
        __syncthreads();
    }
    const float t_hi = s.t_hi;
    const float t_lo = s.t_lo;

    // ---- phase 2: hot stream (full unroll x10, R11/R13 form) ----
    uint32_t nloc = 0;
    uint32_t my_above = 0;
    const uint32_t slotbase = (uint32_t)tid * SLOTS;
    const float NEG = __int_as_float(0xFF800000);
    #pragma unroll
    for (int it = 0; it < 10; it++) {
        int i = tid + it * NT;
        bool valid = i < nvec;
        float4 v = make_float4(NEG, NEG, NEG, NEG);
        if (valid) v = rowp[i];
        float vv[4] = { v.x, v.y, v.z, v.w };
        float ov[4];
        #pragma unroll
        for (int j = 0; j < 4; j++) {
            bool ab = vv[j] >= t_hi;           // sure winner
            bool ge = vv[j] >= t_lo;           // winner or band
            ov[j] = ge ? vv[j] : 0.0f;
            my_above += ab;
            if (ge && !ab) {                   // band candidate
                if (nloc < SLOTS) s.u.sidx[slotbase + nloc] = (uint16_t)(i * 4 + j);
                nloc++;
            }
        }
        if (valid) {
            float4 o; o.x = ov[0]; o.y = ov[1]; o.z = ov[2]; o.w = ov[3];
            outp[i] = o;
        }
    }
    uint32_t nstore = nloc < SLOTS ? nloc : SLOTS;
    if (nloc > SLOTS) s.overflow = 1;

    // reduce c_above
    #pragma unroll
    for (int off = 16; off > 0; off >>= 1)
        my_above += __shfl_down_sync(0xFFFFFFFFu, my_above, off);
    if (lane == 0 && my_above) atomicAdd(&s.c_above, my_above);

    // ---- phase 3: block scan of per-thread band counts ----
    uint32_t incl = nstore;
    #pragma unroll
    for (int off = 1; off < 32; off <<= 1) {
        uint32_t x = __shfl_up_sync(0xFFFFFFFFu, incl, off);
        if (lane >= off) incl += x;
    }
    if (lane == 31) s.wsum[w] = incl;
    __syncthreads();
    if (tid < NWARP) {
        uint32_t c = s.wsum[tid];
        uint32_t inc2 = c;
        #pragma unroll
        for (int off = 1; off < NWARP; off <<= 1) {
            uint32_t x = __shfl_up_sync(0x0000FFFFu, inc2, off);
            if (tid >= off) inc2 += x;
        }
        s.woff[tid] = inc2 - c;
        if (tid == NWARP - 1) s.cand_count = inc2;
    }
    __syncthreads();

    // ---- phase 4: gather band candidates into compact arrays ----
    {
        uint32_t myoff = s.woff[w] + (incl - nstore);
        for (uint32_t n = 0; n < nstore; n++) {
            uint32_t pos = myoff + n;
            if (pos < CAND_CAP) {
                uint16_t idx = s.u.sidx[slotbase + n];
                s.cand[pos] = f2u(rowf[idx]);
                s.cidx[pos] = idx;
            }
        }
    }
    __syncthreads();

    const uint32_t ccount = s.cand_count;
    const uint32_t c_above = s.c_above;
    bool fast = (!s.overflow) && (c_above < KKEEP) &&
                (c_above + ccount >= KKEEP) && (ccount <= CAND_CAP);

    if (!fast) {
        // ================= SLOW PATH (rare; rewrites entire row) =================
        reinterpret_cast<uint4*>(s.u.hist)[tid & 511] = make_uint4(0, 0, 0, 0);
        if (tid == 0) s.cand_count = 0;
        __syncthreads();

        #pragma unroll 1
        for (int it = 0; it < niter; it++) {
            int i = tid + it * NT;
            bool valid = i < nvec;
            uint32_t u0 = 0, u1 = 0, u2 = 0, u3 = 0;
            if (valid) {
                float4 v = rowp[i];
                u0 = f2u(v.x); u1 = f2u(v.y); u2 = f2u(v.z); u3 = f2u(v.w);
            }
            hist_add(s.u.hist, u0 >> 21, valid);
            hist_add(s.u.hist, u1 >> 21, valid);
            hist_add(s.u.hist, u2 >> 21, valid);
            hist_add(s.u.hist, u3 >> 21, valid);
        }
        __syncthreads();
        if (tid < 32) select_from_top(s.u.hist, NBINS, KKEEP, &s.bA, &s.kkA, &s.cntC);
        __syncthreads();
        const uint32_t b1 = s.bA;
        const uint32_t kk1 = s.kkA;

        #pragma unroll 1
        for (int it = 0; it < niter; it++) {
            int i = tid + it * NT;
            if (i >= nvec) break;
            float4 v = rowp[i];
            float vv[4] = { v.x, v.y, v.z, v.w };
            uint32_t uu[4] = { f2u(v.x), f2u(v.y), f2u(v.z), f2u(v.w) };
            float ov[4];
            #pragma unroll
            for (int j = 0; j < 4; j++) {
                uint32_t bin = uu[j] >> 21;
                ov[j] = (bin > b1) ? vv[j] : 0.0f;
                if (bin == b1) {
                    uint32_t pos = atomicAdd(&s.cand_count, 1u);
                    if (pos < CAND_CAP) { s.cand[pos] = uu[j]; s.cidx[pos] = (uint16_t)(i * 4 + j); }
                }
            }
            float4 o; o.x = ov[0]; o.y = ov[1]; o.z = ov[2]; o.w = ov[3];
            outp[i] = o;
        }
        __syncthreads();

        const uint32_t cc2 = s.cand_count;
        const bool use_cand = (cc2 <= CAND_CAP);
        const int nitems = use_cand ? (int)cc2 : DCOLS;
        const int niterB = (nitems + NT - 1) / NT;

        reinterpret_cast<uint4*>(s.u.hist)[tid & 511] = make_uint4(0, 0, 0, 0);
        __syncthreads();
        #pragma unroll 1
        for (int it = 0; it < niterB; it++) {
            int i = tid + it * NT;
            bool valid = i < nitems;
            uint32_t u = 0;
            if (valid) u = use_cand ? s.cand[i] : f2u(rowf[i]);
            valid = valid && (use_cand || ((u >> 21) == b1));
            hist_add(s.u.hist, (u >> 10) & 0x7FFu, valid);
        }
        __syncthreads();
        if (tid < 32) select_from_top(s.u.hist, NBINS, kk1, &s.bB, &s.kkB, &s.cntC);
        __syncthreads();
        const uint32_t b2 = s.bB;
        const uint32_t kk2 = s.kkB;
        const uint32_t pref22 = (b1 << 11) | b2;

        for (int i = tid; i < 1024; i += NT) s.u.hist[i] = 0;
        __syncthreads();
        #pragma unroll 1
        for (int it = 0; it < niterB; it++) {
            int i = tid + it * NT;
            bool valid = i < nitems;
            uint32_t u = 0;
            if (valid) u = use_cand ? s.cand[i] : f2u(rowf[i]);
            valid = valid && ((u >> 10) == pref22);
            hist_add(s.u.hist, u & 0x3FFu, valid);
        }
        __syncthreads();
        if (tid < 32) select_from_top(s.u.hist, 1024, kk2, &s.bC, &s.kkC, &s.cntC);
        __syncthreads();

        const uint32_t u_t = (b1 << 21) | (b2 << 10) | s.bC;
        const uint32_t A = s.kkC;
        const uint32_t T = s.cntC;
        const bool keep_all_ties = (A == T);

        if (use_cand) {
            for (uint32_t q = tid; q < cc2; q += NT) {
                uint32_t u = s.cand[q];
                bool keep = (u > u_t);
                if (!keep && u == u_t) {
                    if (keep_all_ties) keep = true;
                    else {
                        uint32_t rank = 0;
                        for (uint32_t p = 0; p < cc2; p++)
                            rank += (s.cand[p] == u_t && s.cidx[p] < s.cidx[q]);
                        keep = (rank < A);
                    }
                }
                if (keep) outf[s.cidx[q]] = u2f(u);
            }
        } else {
            for (int i = tid; i < DCOLS; i += NT) {
                uint32_t u = f2u(rowf[i]);
                if ((u >> 21) != b1) continue;
                bool keep = (u > u_t);
                if (!keep && u == u_t) {
                    if (keep_all_ties) keep = true;
                    else {
                        uint32_t rank = 0;
                        for (int q = 0; q < i; q++) rank += (f2u(rowf[q]) == u_t);
                        keep = (rank < A);
                    }
                }
                if (keep) outf[i] = u2f(u);
            }
        }
        return;
    }

    // ===== FAST PATH: exact (k - c_above)-th among band candidates =====
    reinterpret_cast<uint4*>(s.u.hist)[tid & 511] = make_uint4(0, 0, 0, 0);
    __syncthreads();

    const uint32_t kk = KKEEP - c_above;
    const int niterC = ((int)ccount + NT - 1) / NT;

    // normalized single-pass bins: band keys lie in [u_lo, u_hi)
    const uint32_t u_lo = f2u(t_lo);
    uint32_t R = f2u(t_hi) - u_lo;
    if (R == 0) R = 1;
    const int shift = __clz(R);

    #pragma unroll 1
    for (int it = 0; it < niterC; it++) {
        int i = tid + it * NT;
        bool valid = i < (int)ccount;
        uint32_t u = valid ? s.cand[i] : 0;
        uint32_t nb = ((u - u_lo) << shift) >> 21;
        hist_add(s.u.hist, nb, valid);
    }
    __syncthreads();
    select2(&s, s.u.hist, NBINS, kk, &s.bA, &s.kkA, &s.cntC, tid);
    const uint32_t nbin = s.bA;
    const uint32_t kk1 = s.kkA;
    const uint32_t cnt1 = s.cntC;

    uint32_t u_t, A, T;

    if (cnt1 <= 32) {
        // collect the cnt1 keys in the target normalized bin (order arbitrary)
        #pragma unroll 1
        for (int it = 0; it < niterC; it++) {
            int i = tid + it * NT;
            if (i < (int)ccount) {
                uint32_t u = s.cand[i];
                uint32_t nb = ((u - u_lo) << shift) >> 21;
                if (nb == nbin) {
                    uint32_t pos = atomicAdd(&s.tcnt, 1u);
                    if (pos < 32) s.segsum[pos] = u;
                }
            }
        }
        __syncthreads();
        // warp-register exact selection among <=32 keys
        if (tid < 32) {
            uint32_t myu = (tid < (int)cnt1) ? s.segsum[tid] : 0;
            uint32_t gt = 0, eq = 0;
            for (uint32_t p = 0; p < cnt1; p++) {
                uint32_t up = __shfl_sync(0xFFFFFFFFu, myu, p);
                gt += (up > myu);
                eq += (up == myu);
            }
            bool sel = (tid < (int)cnt1) && (gt < kk1) && (kk1 <= gt + eq);
            unsigned m = __ballot_sync(0xFFFFFFFFu, sel);
            int l = __ffs(m) - 1;
            if (tid == l) { s.bB = myu; s.kkB = kk1 - gt; s.bC = eq; }
        }
        __syncthreads();
        u_t = s.bB; A = s.kkB; T = s.bC;
    } else {
        // -------- fallback: 3-pass raw-key radix (rare: heavy ties) --------
        reinterpret_cast<uint4*>(s.u.hist)[tid & 511] = make_uint4(0, 0, 0, 0);
        __syncthreads();
        #pragma unroll 1
        for (int it = 0; it < niterC; it++) {
            int i = tid + it * NT;
            bool valid = i < (int)ccount;
            uint32_t u = valid ? s.cand[i] : 0;
            hist_add(s.u.hist, u >> 21, valid);
        }
        __syncthreads();
        select2(&s, s.u.hist, NBINS, kk, &s.bA, &s.kkA, &s.cntC, tid);
        const uint32_t b1 = s.bA;
        const uint32_t kkA = s.kkA;

        reinterpret_cast<uint4*>(s.u.hist)[tid & 511] = make_uint4(0, 0, 0, 0);
        __syncthreads();
        #pragma unroll 1
        for (int it = 0; it < niterC; it++) {
            int i = tid + it * NT;
            bool valid = i < (int)ccount;
            uint32_t u = valid ? s.cand[i] : 0;
            valid = valid && ((u >> 21) == b1);
            hist_add(s.u.hist, (u >> 10) & 0x7FFu, valid);
        }
        __syncthreads();
        select2(&s, s.u.hist, NBINS, kkA, &s.bB, &s.kkB, &s.cntC, tid);
        const uint32_t b2 = s.bB;
        const uint32_t kk2 = s.kkB;
        const uint32_t pref22 = (b1 << 11) | b2;

        for (int i = tid; i < 1024; i += NT) s.u.hist[i] = 0;
        __syncthreads();
        #pragma unroll 1
        for (int it = 0; it < niterC; it++) {
            int i = tid + it * NT;
            bool valid = i < (int)ccount;
            uint32_t u = valid ? s.cand[i] : 0;
            valid = valid && ((u >> 10) == pref22);
            hist_add(s.u.hist, u & 0x3FFu, valid);
        }
        __syncthreads();
        select2(&s, s.u.hist, 1024, kk2, &s.bC, &s.kkC, &s.cntC, tid);

        u_t = (b1 << 21) | (b2 << 10) | s.bC;
        A = s.kkC;
        T = s.cntC;
    }

    const bool keep_all_ties = (A == T);

    // zero band losers (output already holds v for winners + band)
    for (uint32_t q = tid; q < ccount; q += NT) {
        uint32_t u = s.cand[q];
        bool lose = (u < u_t);
        if (!lose && u == u_t && !keep_all_ties) {
            uint32_t rank = 0;
            for (uint32_t p = 0; p < ccount; p++)
                rank += (s.cand[p] == u_t && s.cidx[p] < s.cidx[q]);
            lose = (rank >= A);
        }
        if (lose) outf[s.cidx[q]] = 0.0f;
    }
}

extern "C" void kernel_launch(void* const* d_in, const int* in_sizes, int n_in,
                              void* d_out, int out_size) {
    const float* in = (const float*)d_in[0];
    float* out = (float*)d_out;
    int rows = in_sizes[0] / DCOLS;   // 4096
    wta_kernel<<<rows, NT>>>(in, out, rows);
}

// round 15
// speedup vs baseline: 1.2748x; 1.0878x over previous
#include <cuda_runtime.h>
#include <stdint.h>
#include <math_constants.h>

// WinnerTakeAll: per-row top-k (k=1000), rows of 20000 fp32, 4096 rows.
// NT=512, 4 CTAs/SM. Slot-direct tail: the stream stores candidate KEYS+indices
// in per-thread SMEM slots, so the tail (1 normalized hist pass + select2 +
// warp-register exact select + loser zeroing) runs entirely from SMEM with no
// block scan, no gather, no scattered global loads. Pathological bins (>32) or
// boundary ties -> full exact slow path (rewrites row); count-gate violations
// (c_above>=k, c_above+ccount<k, slot overflow) -> same slow path.

#define DCOLS    20000
#define KKEEP    1000u
#define NT       512
#define NWARP    16
#define NBINS    2048
#define SLOTS    12
#define CAND_CAP 1024
#define ZHI      1.751f
#define ZLO      1.514f

struct Smem {
    union {
        struct {                       // fast path: per-thread slots
            uint32_t skey[NT * SLOTS]; // 24576 B
            uint16_t sidx[NT * SLOTS]; // 12288 B
        } f;
        struct {                       // slow path: compact candidate arrays
            uint32_t cand[CAND_CAP];   // 4096 B
            uint16_t cidx[CAND_CAP];   // 2048 B
        } sp;
    } u;                               // 36864 B
    uint32_t hist[NBINS];              // 8192 B (NOT unioned with slots)
    uint32_t segsum[256];              // 1 KB (select2 scratch + tie-collect)
    float    redsum[NWARP], redsq[NWARP];
    float    t_hi, t_lo;
    uint32_t cand_count, overflow, c_above, tcnt;
    uint32_t bA, kkA, bB, kkB, bC, kkC, cntC;
};

__device__ __forceinline__ uint32_t f2u(float f) {
    uint32_t b = __float_as_uint(f);
    return b ^ ((b & 0x80000000u) ? 0xFFFFFFFFu : 0x80000000u);
}
__device__ __forceinline__ float u2f(uint32_t u) {
    uint32_t b = (u & 0x80000000u) ? (u ^ 0x80000000u) : (u ^ 0xFFFFFFFFu);
    return __uint_as_float(b);
}

// Warp-aggregated histogram add (ALL 32 lanes participate). Slow path only.
__device__ __forceinline__ void hist_add(uint32_t* hist, uint32_t bin, bool valid) {
    uint32_t key = valid ? bin : 0xFFFFFFFFu;
    unsigned m = __match_any_sync(0xFFFFFFFFu, key);
    int leader = __ffs(m) - 1;
    if (valid && (int)(threadIdx.x & 31) == leader)
        atomicAdd(&hist[bin], (uint32_t)__popc(m));
}

// Serial top-down scan (slow path only; warp 0).
__device__ __forceinline__ void select_from_top(const uint32_t* hist, int nbins, uint32_t kk,
                                                uint32_t* out_bin, uint32_t* out_kk, uint32_t* out_cnt) {
    int lane = threadIdx.x & 31;
    uint32_t cum = 0;
    for (int base = nbins - 32; base >= 0; base -= 32) {
        uint32_t v = hist[base + 31 - lane];
        uint32_t incl = v;
        #pragma unroll
        for (int off = 1; off < 32; off <<= 1) {
            uint32_t t = __shfl_up_sync(0xFFFFFFFFu, incl, off);
            if (lane >= off) incl += t;
        }
        uint32_t total = __shfl_sync(0xFFFFFFFFu, incl, 31);
        unsigned hm = __ballot_sync(0xFFFFFFFFu, cum + incl >= kk);
        if (hm) {
            int l = __ffs(hm) - 1;
            if (lane == l) {
                *out_bin = (uint32_t)(base + 31 - l);
                *out_kk  = kk - cum - (incl - v);
                *out_cnt = v;
            }
            return;
        }
        cum += total;
    }
    if (lane == 0) { *out_bin = 0; *out_kk = 1; *out_cnt = 1; }
}

// Block-parallel select: segment sums (8 bins/seg), then warp 0 scans segments.
__device__ __forceinline__ void select2(Smem* s, const uint32_t* hist, int nbins, uint32_t kk,
                                        uint32_t* out_bin, uint32_t* out_kk, uint32_t* out_cnt,
                                        int tid) {
    int nseg = nbins >> 3;
    const uint4* h4 = reinterpret_cast<const uint4*>(hist);
    for (int i = tid; i < nseg; i += NT) {
        uint4 x = h4[2 * i], y = h4[2 * i + 1];
        s->segsum[i] = x.x + x.y + x.z + x.w + y.x + y.y + y.z + y.w;
    }
    __syncthreads();
    if (tid < 32) {
        int lane = tid;
        uint32_t cum = 0;
        bool done = false;
        for (int base = nseg - 32; base >= 0 && !done; base -= 32) {
            uint32_t v = s->segsum[base + 31 - lane];
            uint32_t incl = v;
            #pragma unroll
            for (int off = 1; off < 32; off <<= 1) {
                uint32_t t = __shfl_up_sync(0xFFFFFFFFu, incl, off);
                if (lane >= off) incl += t;
            }
            uint32_t total = __shfl_sync(0xFFFFFFFFu, incl, 31);
            unsigned hm = __ballot_sync(0xFFFFFFFFu, cum + incl >= kk);
            if (hm) {
                int l = __ffs(hm) - 1;
                if (lane == l) {
                    int seg = base + 31 - l;
                    uint32_t kk_s = kk - cum - (incl - v);
                    for (int b = seg * 8 + 7; b >= seg * 8; b--) {
                        uint32_t c = hist[b];
                        if (kk_s <= c) { *out_bin = (uint32_t)b; *out_kk = kk_s; *out_cnt = c; break; }
                        kk_s -= c;
                    }
                }
                done = true;
            }
            cum += total;
        }
        if (!done && lane == 0) { *out_bin = 0; *out_kk = 1; *out_cnt = 1; }
    }
    __syncthreads();
}

extern "C" __global__ void __launch_bounds__(NT, 4)
wta_kernel(const float* __restrict__ in, float* __restrict__ out, int rows) {
    __shared__ Smem s;

    const int row = blockIdx.x;
    if (row >= rows) return;
    const int tid = threadIdx.x;
    const int lane = tid & 31;
    const int w = tid >> 5;

    const float*  rowf = in + (size_t)row * DCOLS;
    const float4* rowp = reinterpret_cast<const float4*>(rowf);
    float4* outp = reinterpret_cast<float4*>(out + (size_t)row * DCOLS);
    float*  outf = out + (size_t)row * DCOLS;
    const int nvec = DCOLS / 4;                 // 5000
    const int niter = (nvec + NT - 1) / NT;     // 10

    if (tid == 0) { s.cand_count = 0; s.overflow = 0; s.c_above = 0; s.tcnt = 0; }
    // clear hist now (no longer aliased with slots): 512 * 16B = 8KB
    reinterpret_cast<uint4*>(s.hist)[tid] = make_uint4(0, 0, 0, 0);

    // ---- phase 1: thresholds from sample mean/std (2048 samples) ----
    {
        float4 a = rowp[tid];
        float sum = a.x + a.y + a.z + a.w;
        float sq = fmaf(a.x, a.x, fmaf(a.y, a.y, fmaf(a.z, a.z, a.w * a.w)));
        #pragma unroll
        for (int off = 16; off > 0; off >>= 1) {
            sum += __shfl_down_sync(0xFFFFFFFFu, sum, off);
            sq  += __shfl_down_sync(0xFFFFFFFFu, sq,  off);
        }
        if (lane == 0) { s.redsum[w] = sum; s.redsq[w] = sq; }
        __syncthreads();
        if (tid == 0) {
            float ts = 0.f, tq = 0.f;
            #pragma unroll
            for (int i = 0; i < NWARP; i++) { ts += s.redsum[i]; tq += s.redsq[i]; }
            float mu = ts * (1.0f / 2048.0f);
            float var = tq * (1.0f / 2048.0f) - mu * mu;
            float sd = sqrtf(fmaxf(var, 0.0f));
            s.t_hi = fmaf(ZHI, sd, mu);
            s.t_lo = fmaf(ZLO, sd, mu);
        }
        __syncthreads();
    }
    const float t_hi = s.t_hi;
    const float t_lo = s.t_lo;

    // ---- phase 2: hot stream (full unroll x10); candidates -> key+idx slots ----
    uint32_t nloc = 0;
    uint32_t my_above = 0;
    const uint32_t slotbase = (uint32_t)tid * SLOTS;
    const float NEG = __int_as_float(0xFF800000);
    #pragma unroll
    for (int it = 0; it < 10; it++) {
        int i = tid + it * NT;
        bool valid = i < nvec;
        float4 v = make_float4(NEG, NEG, NEG, NEG);
        if (valid) v = rowp[i];
        float vv[4] = { v.x, v.y, v.z, v.w };
        float ov[4];
        #pragma unroll
        for (int j = 0; j < 4; j++) {
            bool ab = vv[j] >= t_hi;           // sure winner
            bool ge = vv[j] >= t_lo;           // winner or band
            ov[j] = ge ? vv[j] : 0.0f;
            my_above += ab;
            if (ge && !ab) {                   // band candidate: store key + index
                if (nloc < SLOTS) {
                    s.u.f.skey[slotbase + nloc] = f2u(vv[j]);
                    s.u.f.sidx[slotbase + nloc] = (uint16_t)(i * 4 + j);
                }
                nloc++;
            }
        }
        if (valid) {
            float4 o; o.x = ov[0]; o.y = ov[1]; o.z = ov[2]; o.w = ov[3];
            outp[i] = o;
        }
    }
    uint32_t nstore = nloc < SLOTS ? nloc : SLOTS;
    if (nloc > SLOTS) s.overflow = 1;

    // ---- reduce c_above and ccount (one warp-reduce each, one atomic/warp) ----
    uint32_t my_band = nstore;
    #pragma unroll
    for (int off = 16; off > 0; off >>= 1) {
        my_above += __shfl_down_sync(0xFFFFFFFFu, my_above, off);
        my_band  += __shfl_down_sync(0xFFFFFFFFu, my_band,  off);
    }
    if (lane == 0) {
        if (my_above) atomicAdd(&s.c_above, my_above);
        if (my_band)  atomicAdd(&s.cand_count, my_band);
    }
    __syncthreads();

    const uint32_t ccount = s.cand_count;
    const uint32_t c_above = s.c_above;
    bool need_slow = !((!s.overflow) && (c_above < KKEEP) && (c_above + ccount >= KKEEP));

    if (!need_slow) {
        // ===== FAST TAIL: slot-direct, SMEM only =====
        const uint32_t kk = KKEEP - c_above;
        const uint32_t u_lo = f2u(t_lo);
        uint32_t R = f2u(t_hi) - u_lo;
        if (R == 0) R = 1;
        const int shift = __clz(R);

        // 1-pass normalized histogram from slots (plain atomics; bins ~unique)
        for (uint32_t n = 0; n < nstore; n++) {
            uint32_t u = s.u.f.skey[slotbase + n];
            uint32_t nb = ((u - u_lo) << shift) >> 21;
            atomicAdd(&s.hist[nb], 1u);
        }
        __syncthreads();
        select2(&s, s.hist, NBINS, kk, &s.bA, &s.kkA, &s.cntC, tid);
        const uint32_t nbin = s.bA;
        const uint32_t kk1 = s.kkA;
        const uint32_t cnt1 = s.cntC;

        if (cnt1 > 32) {
            need_slow = true;                   // pathological tie mass in one bin
        } else {
            // collect the <=32 keys of the target bin
            for (uint32_t n = 0; n < nstore; n++) {
                uint32_t u = s.u.f.skey[slotbase + n];
                uint32_t nb = ((u - u_lo) << shift) >> 21;
                if (nb == nbin) {
                    uint32_t pos = atomicAdd(&s.tcnt, 1u);
                    s.segsum[pos] = u;          // pos < 32 guaranteed (cnt1<=32)
                }
            }
            __syncthreads();
            // warp-register exact selection among <=32 keys
            if (tid < 32) {
                uint32_t myu = (tid < (int)cnt1) ? s.segsum[tid] : 0;
                uint32_t gt = 0, eq = 0;
                for (uint32_t p = 0; p < cnt1; p++) {
                    uint32_t up = __shfl_sync(0xFFFFFFFFu, myu, p);
                    gt += (up > myu);
                    eq += (up == myu);
                }
                bool sel = (tid < (int)cnt1) && (gt < kk1) && (kk1 <= gt + eq);
                unsigned m = __ballot_sync(0xFFFFFFFFu, sel);
                int l = __ffs(m) - 1;
                if (tid == l) { s.bB = myu; s.kkB = kk1 - gt; s.bC = eq; }
            }
            __syncthreads();
            const uint32_t u_t = s.bB;
            const uint32_t A = s.kkB;
            const uint32_t T = s.bC;
            if (A != T) {
                need_slow = true;               // ties straddle boundary (rare)
            } else {
                // zero losers straight from slots (output holds v for all >=t_lo)
                for (uint32_t n = 0; n < nstore; n++) {
                    uint32_t u = s.u.f.skey[slotbase + n];
                    if (u < u_t) outf[s.u.f.sidx[slotbase + n]] = 0.0f;
                }
                return;
            }
        }
    }

    // ================= SLOW PATH (rare; rewrites entire row) =================
    __syncthreads();
    reinterpret_cast<uint4*>(s.hist)[tid] = make_uint4(0, 0, 0, 0);
    if (tid == 0) s.cand_count = 0;
    __syncthreads();

    #pragma unroll 1
    for (int it = 0; it < niter; it++) {
        int i = tid + it * NT;
        bool valid = i < nvec;
        uint32_t u0 = 0, u1 = 0, u2 = 0, u3 = 0;
        if (valid) {
            float4 v = rowp[i];
            u0 = f2u(v.x); u1 = f2u(v.y); u2 = f2u(v.z); u3 = f2u(v.w);
        }
        hist_add(s.hist, u0 >> 21, valid);
        hist_add(s.hist, u1 >> 21, valid);
        hist_add(s.hist, u2 >> 21, valid);
        hist_add(s.hist, u3 >> 21, valid);
    }
    __syncthreads();
    if (tid < 32) select_from_top(s.hist, NBINS, KKEEP, &s.bA, &s.kkA, &s.cntC);
    __syncthreads();
    const uint32_t b1 = s.bA;
    const uint32_t kk1s = s.kkA;

    #pragma unroll 1
    for (int it = 0; it < niter; it++) {
        int i = tid + it * NT;
        if (i >= nvec) break;
        float4 v = rowp[i];
        float vv[4] = { v.x, v.y, v.z, v.w };
        uint32_t uu[4] = { f2u(v.x), f2u(v.y), f2u(v.z), f2u(v.w) };
        float ov[4];
        #pragma unroll
        for (int j = 0; j < 4; j++) {
            uint32_t bin = uu[j] >> 21;
            ov[j] = (bin > b1) ? vv[j] : 0.0f;
            if (bin == b1) {
                uint32_t pos = atomicAdd(&s.cand_count, 1u);
                if (pos < CAND_CAP) { s.u.sp.cand[pos] = uu[j]; s.u.sp.cidx[pos] = (uint16_t)(i * 4 + j); }
            }
        }
        float4 o; o.x = ov[0]; o.y = ov[1]; o.z = ov[2]; o.w = ov[3];
        outp[i] = o;
    }
    __syncthreads();

    const uint32_t cc2 = s.cand_count;
    const bool use_cand = (cc2 <= CAND_CAP);
    const int nitems = use_cand ? (int)cc2 : DCOLS;
    const int niterB = (nitems + NT - 1) / NT;

    reinterpret_cast<uint4*>(s.hist)[tid] = make_uint4(0, 0, 0, 0);
    __syncthreads();
    #pragma unroll 1
    for (int it = 0; it < niterB; it++) {
        int i = tid + it * NT;
        bool valid = i < nitems;
        uint32_t u = 0;
        if (valid) u = use_cand ? s.u.sp.cand[i] : f2u(rowf[i]);
        valid = valid && (use_cand || ((u >> 21) == b1));
        hist_add(s.hist, (u >> 10) & 0x7FFu, valid);
    }
    __syncthreads();
    if (tid < 32) select_from_top(s.hist, NBINS, kk1s, &s.bB, &s.kkB, &s.cntC);
    __syncthreads();
    const uint32_t b2 = s.bB;
    const uint32_t kk2 = s.kkB;
    const uint32_t pref22 = (b1 << 11) | b2;

    for (int i = tid; i < 1024; i += NT) s.hist[i] = 0;
    __syncthreads();
    #pragma unroll 1
    for (int it = 0; it < niterB; it++) {
        int i = tid + it * NT;
        bool valid = i < nitems;
        uint32_t u = 0;
        if (valid) u = use_cand ? s.u.sp.cand[i] : f2u(rowf[i]);
        valid = valid && ((u >> 10) == pref22);
        hist_add(s.hist, u & 0x3FFu, valid);
    }
    __syncthreads();
    if (tid < 32) select_from_top(s.hist, 1024, kk2, &s.bC, &s.kkC, &s.cntC);
    __syncthreads();

    const uint32_t u_t = (b1 << 21) | (b2 << 10) | s.bC;
    const uint32_t A = s.kkC;
    const uint32_t T = s.cntC;
    const bool keep_all_ties = (A == T);

    if (use_cand) {
        for (uint32_t q = tid; q < cc2; q += NT) {
            uint32_t u = s.u.sp.cand[q];
            bool keep = (u > u_t);
            if (!keep && u == u_t) {
                if (keep_all_ties) keep = true;
                else {
                    uint32_t rank = 0;
                    for (uint32_t p = 0; p < cc2; p++)
                        rank += (s.u.sp.cand[p] == u_t && s.u.sp.cidx[p] < s.u.sp.cidx[q]);
                    keep = (rank < A);
                }
            }
            if (keep) outf[s.u.sp.cidx[q]] = u2f(u);
        }
    } else {
        for (int i = tid; i < DCOLS; i += NT) {
            uint32_t u = f2u(rowf[i]);
            if ((u >> 21) != b1) continue;
            bool keep = (u > u_t);
            if (!keep && u == u_t) {
                if (keep_all_ties) keep = true;
                else {
                    uint32_t rank = 0;
                    for (int q = 0; q < i; q++) rank += (f2u(rowf[q]) == u_t);
                    keep = (rank < A);
                }
            }
            if (keep) outf[i] = u2f(u);
        }
    }
}

extern "C" void kernel_launch(void* const* d_in, const int* in_sizes, int n_in,
                              void* d_out, int out_size) {
    const float* in = (const float*)d_in[0];
    float* out = (float*)d_out;
    int rows = in_sizes[0] / DCOLS;   // 4096
    wta_kernel<<<rows, NT>>>(in, out, rows);
}